// round 9
// baseline (speedup 1.0000x reference)
#include <cuda_runtime.h>
#include <cstdint>

// ---------------------------------------------------------------------------
// SE3Net fused single-kernel: 148 blocks = one wave.
//   blocks 0..143 : conv (36 per batch). Stage feat/geo -> spin on table flag
//                   -> copy table -> pair mainloop -> per-batch epilogue.
//   blocks 144..147: grid MLP (8 rows each, NPTS=32). Weights via 4-deep
//                   cp.async.bulk ring; (j-quarter, column) lanes; shfl
//                   combine; ONE barrier/layer. Last block releases flag.
// All counters/flags self-reset for graph replay. Deterministic.
// ---------------------------------------------------------------------------

#define NPTS    32
#define OCP     52
#define CIN     23
#define FSTR    24
#define NB      286
#define BATCH   4
#define HDIM    100
#define CPAD    104
#define NLAYERS 49
#define RMAX    4.5f
#define DELTA   (RMAX / (float)(NPTS - 1))
#define INV_DELTA ((float)(NPTS - 1) / RMAX)

#define TM 8                      // grid rows per MLP block
#define NMLP (NPTS / TM)          // 4 MLP blocks
#define JPQ 25                    // j per quarter
#define THREADS 416               // 13 warps (both roles)

#define ATOMS_PB 8
#define BLK_PER_BATCH 36          // 36*8 = 288 >= 286
#define NCONV (BLK_PER_BATCH * BATCH)   // 144
#define NGRID (NCONV + NMLP)            // 148

#define LAYER_FLOATS (HDIM * HDIM)      // 10000
#define LAYER_BYTES (LAYER_FLOATS * 4)  // 40000
#define RING 4
#define DSMEM_BYTES 160032              // ring (160000) + overflow pad

typedef unsigned long long ull;

__device__ __align__(16) float g_table[NPTS * OCP];
__device__ float g_rows[BATCH * NB * 2];
__device__ int   g_ctr[BATCH];
__device__ int   g_flag;        // table ready
__device__ int   g_mlp_done;
__device__ int   g_done;        // epilogues done

__device__ __forceinline__ ull ffma2(ull a, ull b, ull c) {
    ull d;
    asm("fma.rn.f32x2 %0, %1, %2, %3;" : "=l"(d) : "l"(a), "l"(b), "l"(c));
    return d;
}
__device__ __forceinline__ ull add2(ull a, ull b) {
    ull d;
    asm("add.rn.f32x2 %0, %1, %2;" : "=l"(d) : "l"(a), "l"(b));
    return d;
}
__device__ __forceinline__ ull pack2(float lo, float hi) {
    ull d;
    asm("mov.b64 %0, {%1, %2};" : "=l"(d) : "f"(lo), "f"(hi));
    return d;
}
__device__ __forceinline__ float2 unpack2(ull v) {
    float lo, hi;
    asm("mov.b64 {%0, %1}, %2;" : "=f"(lo), "=f"(hi) : "l"(v));
    return make_float2(lo, hi);
}
__device__ __forceinline__ uint32_t s2u(const void* p) {
    return (uint32_t)__cvta_generic_to_shared(p);
}
__device__ __forceinline__ void mbar_init(uint32_t m, uint32_t cnt) {
    asm volatile("mbarrier.init.shared.b64 [%0], %1;" :: "r"(m), "r"(cnt)
                 : "memory");
}
__device__ __forceinline__ void mbar_expect_tx(uint32_t m, uint32_t bytes) {
    asm volatile("mbarrier.arrive.expect_tx.shared.b64 _, [%0], %1;"
                 :: "r"(m), "r"(bytes) : "memory");
}
__device__ __forceinline__ void bulk_g2s(uint32_t dst, const void* src,
                                         uint32_t bytes, uint32_t m) {
    asm volatile(
        "cp.async.bulk.shared::cta.global.mbarrier::complete_tx::bytes "
        "[%0], [%1], %2, [%3];"
        :: "r"(dst), "l"(src), "r"(bytes), "r"(m) : "memory");
}
__device__ __forceinline__ void mbar_wait(uint32_t m, uint32_t parity) {
    asm volatile(
        "{\n\t"
        ".reg .pred P;\n"
        "W%=:\n\t"
        "mbarrier.try_wait.parity.acquire.cta.shared::cta.b64 P, [%0], %1, 0x989680;\n\t"
        "@P bra D%=;\n\t"
        "bra W%=;\n"
        "D%=:\n\t"
        "}"
        :: "r"(m), "r"(parity) : "memory");
}
__device__ __forceinline__ float bump(float x) {
    float ax = fabsf(x);
    if (ax >= 1.0f) return 0.0f;
    float c = cosf(1.5707963267948966f * x);
    return c * c;
}

__global__ void __launch_bounds__(THREADS) fused_kernel(
    const float* __restrict__ features,   // [B,N,23]
    const float* __restrict__ geometry,   // [B,N,3]
    const float* __restrict__ w_in,       // [3,100]
    const float* __restrict__ w_h,        // [49,100,100]
    const float* __restrict__ w_out,      // [100,46]
    const float* __restrict__ lin_w,      // [2]
    const float* __restrict__ lin_b,      // [1]
    float* __restrict__ out)              // [B]
{
    extern __shared__ __align__(16) float dyn[];    // ring (mlp) / stage (conv)
    __shared__ __align__(16) ull h2[2][CPAD][TM / 2];
    __shared__ float red0[THREADS];
    __shared__ float red1[THREADS];
    __shared__ __align__(8) ull mbar[RING];
    __shared__ int last_flag;

    const int tid = threadIdx.x;
    const int wrp = tid >> 5;
    const int ln  = tid & 31;
    const int bid = blockIdx.x;

    // =======================================================================
    // MLP role
    // =======================================================================
    if (bid >= NCONV) {
        const int m0 = (bid - NCONV) * TM;
        const int q  = ln >> 3;                 // j-quarter 0..3
        const int c  = wrp * 8 + (ln & 7);      // column 0..103

        if (tid == 0) {
#pragma unroll
            for (int s = 0; s < RING; s++) mbar_init(s2u(&mbar[s]), 1);
        }
        __syncthreads();
        if (tid == 0) {
#pragma unroll
            for (int s = 0; s < RING; s++) {
                mbar_expect_tx(s2u(&mbar[s]), LAYER_BYTES);
                bulk_g2s(s2u(dyn + s * LAYER_FLOATS),
                         w_h + (size_t)s * LAYER_FLOATS, LAYER_BYTES,
                         s2u(&mbar[s]));
            }
        }

        // ---- layer 0: basis -> h (q==0 lanes cover each c once) ----
        if (q == 0) {
            ull hv[TM / 2] = {0ULL, 0ULL, 0ULL, 0ULL};
            if (c < HDIM) {
                const float inv_sqrt3 = 0.57735026918962576f;
                float wi0 = w_in[c], wi1 = w_in[HDIM + c],
                      wi2 = w_in[2 * HDIM + c];
#pragma unroll
                for (int p = 0; p < TM / 2; p++) {
                    float v[2];
#pragma unroll
                    for (int k = 0; k < 2; k++) {
                        float rr = (float)(m0 + 2 * p + k) * DELTA;
                        float b0 = bump(rr * (1.0f / 1.5f));
                        float b1 = bump((rr - 1.5f) * (1.0f / 1.5f));
                        float b2 = bump((rr - 3.0f) * (1.0f / 1.5f));
                        float a = (b0 * wi0 + b1 * wi1 + b2 * wi2) * inv_sqrt3;
                        v[k] = fmaxf(a, 0.0f);
                    }
                    hv[p] = pack2(v[0], v[1]);
                }
            }
#pragma unroll
            for (int p = 0; p < TM / 2; p++) h2[0][c][p] = hv[p];
        }
        __syncthreads();

        int cur = 0;
#pragma unroll 1
        for (int l = 0; l < NLAYERS; l++) {
            mbar_wait(s2u(&mbar[l & 3]), (l >> 2) & 1);

            const float* __restrict__ ws = dyn + (l & 3) * LAYER_FLOATS + c;
            ull A0 = 0, A1 = 0, A2 = 0, A3 = 0;
#pragma unroll
            for (int jj = 0; jj < JPQ; jj++) {
                int j = q * JPQ + jj;
                float wv = ws[j * HDIM];
                ull pw = pack2(wv, wv);
                ulonglong2 hA = *reinterpret_cast<const ulonglong2*>(
                    &h2[cur][j][0]);
                ulonglong2 hB = *reinterpret_cast<const ulonglong2*>(
                    &h2[cur][j][2]);
                A0 = ffma2(hA.x, pw, A0);
                A1 = ffma2(hA.y, pw, A1);
                A2 = ffma2(hB.x, pw, A2);
                A3 = ffma2(hB.y, pw, A3);
            }
#pragma unroll
            for (int off = 8; off <= 16; off <<= 1) {
                A0 = add2(A0, __shfl_xor_sync(0xffffffffu, A0, off));
                A1 = add2(A1, __shfl_xor_sync(0xffffffffu, A1, off));
                A2 = add2(A2, __shfl_xor_sync(0xffffffffu, A2, off));
                A3 = add2(A3, __shfl_xor_sync(0xffffffffu, A3, off));
            }
            if (q == 0) {
                ull o0 = 0, o1 = 0, o2 = 0, o3 = 0;
                if (c < HDIM) {
                    float2 v0 = unpack2(A0), v1 = unpack2(A1);
                    float2 v2 = unpack2(A2), v3 = unpack2(A3);
                    o0 = pack2(fmaxf(v0.x * 0.1f, 0.f), fmaxf(v0.y * 0.1f, 0.f));
                    o1 = pack2(fmaxf(v1.x * 0.1f, 0.f), fmaxf(v1.y * 0.1f, 0.f));
                    o2 = pack2(fmaxf(v2.x * 0.1f, 0.f), fmaxf(v2.y * 0.1f, 0.f));
                    o3 = pack2(fmaxf(v3.x * 0.1f, 0.f), fmaxf(v3.y * 0.1f, 0.f));
                }
                h2[cur ^ 1][c][0] = o0;
                h2[cur ^ 1][c][1] = o1;
                h2[cur ^ 1][c][2] = o2;
                h2[cur ^ 1][c][3] = o3;
            }
            __syncthreads();   // h ready AND all reads of ring slot done

            if (tid == 0 && l + RING < NLAYERS) {
                uint32_t mb = s2u(&mbar[l & 3]);
                mbar_expect_tx(mb, LAYER_BYTES);
                bulk_g2s(s2u(dyn + (l & 3) * LAYER_FLOATS),
                         w_h + (size_t)(l + RING) * LAYER_FLOATS,
                         LAYER_BYTES, mb);
            }
            cur ^= 1;
        }

        // ---- output layer: 46 outputs x 8 rows = 368 threads ----
        if (tid < 2 * CIN * TM) {
            int o = tid % (2 * CIN);
            int r = tid / (2 * CIN);
            const float* hp = reinterpret_cast<const float*>(&h2[cur][0][0])
                              + (r >> 1) * 2 + (r & 1);
            float acc = 0.0f;
#pragma unroll 4
            for (int j = 0; j < HDIM; j++)
                acc = fmaf(hp[j * (TM)], w_out[j * (2 * CIN) + o], acc);
            const float SCALE = 0.1f * 0.28209479177387814f * 0.5f;
            int co = o % CIN, oo = o / CIN;
            g_table[(m0 + r) * OCP + co * 2 + oo] = acc * SCALE;
        }
        for (int z = tid; z < TM * (OCP - 2 * CIN); z += THREADS) {
            int r = z / (OCP - 2 * CIN);
            int pos = 2 * CIN + z % (OCP - 2 * CIN);
            g_table[(m0 + r) * OCP + pos] = 0.0f;
        }

        __threadfence();
        __syncthreads();
        if (tid == 0) {
            int prev = atomicAdd(&g_mlp_done, 1);
            if (prev == NMLP - 1) atomicExch(&g_flag, 1);   // release table
        }
        return;
    }

    // =======================================================================
    // Conv role
    // =======================================================================
    float* table_s = dyn;                       // NPTS*OCP = 1664 floats
    float* feat_s  = dyn + NPTS * OCP;          // NB*FSTR  = 6864
    float* geo_s   = feat_s + NB * FSTR;        // NB*4     = 1144

    const int b = bid / BLK_PER_BATCH;
    const int grp = bid % BLK_PER_BATCH;

    // ---- stage features/geometry NOW (independent of MLP) ----
    const float* fb = features + (size_t)b * NB * CIN;
    for (int jr = wrp; jr < NB; jr += THREADS / 32) {
        if (ln < FSTR)
            feat_s[jr * FSTR + ln] = (ln < CIN) ? fb[jr * CIN + ln] : 0.0f;
    }
    const float* gb = geometry + (size_t)b * NB * 3;
    for (int k = tid; k < NB * 4; k += THREADS) {
        int j = k >> 2, d = k & 3;
        geo_s[k] = (d < 3) ? gb[j * 3 + d] : 0.0f;
    }

    // ---- wait for table ----
    if (tid == 0) {
        int v;
        do {
            asm volatile("ld.acquire.gpu.global.s32 %0, [%1];"
                         : "=r"(v) : "l"(&g_flag) : "memory");
            if (!v) __nanosleep(200);
        } while (!v);
    }
    __syncthreads();

    // ---- copy table (1664 floats = 416 float4: one pass) ----
    if (tid < (NPTS * OCP) / 4)
        reinterpret_cast<float4*>(table_s)[tid] =
            reinterpret_cast<const float4*>(g_table)[tid];
    __syncthreads();

    // ---- pair mainloop: warp-per-atom (warps 0..7) ----
    const int i = grp * ATOMS_PB + wrp;
    if (wrp < ATOMS_PB && i < NB) {
        float gx = geo_s[i * 4], gy = geo_s[i * 4 + 1], gz = geo_s[i * 4 + 2];
        ull acc = 0ULL;
        for (int j = ln; j < NB; j += 32) {
            float4 g4 = *reinterpret_cast<const float4*>(geo_s + j * 4);
            float dx = g4.x - gx, dy = g4.y - gy, dz = g4.z - gz;
            float r = sqrtf(fmaf(dx, dx, fmaf(dy, dy, fmaf(dz, dz, 1e-12f))));
            int u = __float2int_rn(r * INV_DELTA);
            if (u < NPTS) {
                const ulonglong2* __restrict__ T =
                    reinterpret_cast<const ulonglong2*>(table_s + u * OCP);
                const float4* __restrict__ f4 =
                    reinterpret_cast<const float4*>(feat_s + j * FSTR);
                ull d0 = 0ULL, d1 = 0ULL;
#pragma unroll
                for (int k = 0; k < 6; k++) {
                    float4 f = f4[k];
                    ulonglong2 t0 = T[2 * k];
                    ulonglong2 t1 = T[2 * k + 1];
                    d0 = ffma2(t0.x, pack2(f.x, f.x), d0);
                    d1 = ffma2(t0.y, pack2(f.y, f.y), d1);
                    d0 = ffma2(t1.x, pack2(f.z, f.z), d0);
                    d1 = ffma2(t1.y, pack2(f.w, f.w), d1);
                }
                acc = add2(acc, add2(d0, d1));
            }
        }
        float2 av = unpack2(acc);
        float a0 = av.x, a1 = av.y;
#pragma unroll
        for (int off = 16; off > 0; off >>= 1) {
            a0 += __shfl_xor_sync(0xffffffffu, a0, off);
            a1 += __shfl_xor_sync(0xffffffffu, a1, off);
        }
        if (ln == 0) {   // single writer per (b,i): direct store
            g_rows[(b * NB + i) * 2 + 0] = fmaxf(a0, 0.0f);
            g_rows[(b * NB + i) * 2 + 1] = fmaxf(a1, 0.0f);
        }
    }

    // ---- per-batch epilogue: relu'ed rows -> mean -> linear ----
    __threadfence();
    __syncthreads();
    if (tid == 0)
        last_flag = (atomicAdd(&g_ctr[b], 1) == BLK_PER_BATCH - 1) ? 1 : 0;
    __syncthreads();
    if (last_flag) {
        __threadfence();
        float s0 = 0.f, s1 = 0.f;
        for (int k = tid; k < NB; k += THREADS) {
            s0 += g_rows[(b * NB + k) * 2 + 0];
            s1 += g_rows[(b * NB + k) * 2 + 1];
        }
        red0[tid] = s0; red1[tid] = s1;
        __syncthreads();
        if (tid < THREADS - 256) {          // fold 416 -> 256
            red0[tid] += red0[tid + 256];
            red1[tid] += red1[tid + 256];
        }
        __syncthreads();
#pragma unroll
        for (int s = 128; s > 0; s >>= 1) {
            if (tid < s) { red0[tid] += red0[tid + s]; red1[tid] += red1[tid + s]; }
            __syncthreads();
        }
        if (tid == 0) {
            out[b] = (red0[0] * lin_w[0] + red1[0] * lin_w[1])
                     * (1.0f / (float)NB) + lin_b[0];
            g_ctr[b] = 0;                                   // replay reset
            int p = atomicAdd(&g_done, 1);
            if (p == BATCH - 1) {                           // final reset
                g_flag = 0;
                g_mlp_done = 0;
                g_done = 0;
            }
        }
    }
}

// ---------------------------------------------------------------------------
extern "C" void kernel_launch(void* const* d_in, const int* in_sizes, int n_in,
                              void* d_out, int out_size) {
    int o = 0;
    if (n_in >= 4 && in_sizes[2] == 1) o = 1;   // num_atoms scalar present

    const float* features = (const float*)d_in[0];
    const float* geometry = (const float*)d_in[1];
    const float* w_in     = (const float*)d_in[2 + o];
    const float* w_h      = (const float*)d_in[3 + o];
    const float* w_out    = (const float*)d_in[4 + o];
    const float* lin_w    = (const float*)d_in[5 + o];
    const float* lin_b    = (const float*)d_in[6 + o];

    cudaFuncSetAttribute(fused_kernel,
                         cudaFuncAttributeMaxDynamicSharedMemorySize,
                         DSMEM_BYTES);
    fused_kernel<<<NGRID, THREADS, DSMEM_BYTES>>>(
        features, geometry, w_in, w_h, w_out, lin_w, lin_b, (float*)d_out);
}